// round 3
// baseline (speedup 1.0000x reference)
#include <cuda_runtime.h>
#include <stdint.h>

// Output nodes = N_NODES / 3 = 1,000,000
#define MAX_OUT_NODES 1000000
__device__ float g_agg[MAX_OUT_NODES];

// ---------------------------------------------------------------------------
// Kernel 1: zero the aggregation scratch (vectorized)
// ---------------------------------------------------------------------------
__global__ void zero_agg_kernel(int m4) {
    int i = blockIdx.x * blockDim.x + threadIdx.x;
    if (i < m4) reinterpret_cast<float4*>(g_agg)[i] = make_float4(0.f, 0.f, 0.f, 0.f);
}

// ---------------------------------------------------------------------------
// Kernel 2: edge scatter, 8 edges per thread.
// - edge rows (src, dst) streamed with __ldcs (evict-first) so the L2 keeps
//   the reused working sets: x (12 MB) and g_agg (4 MB).
// - only edges with dst % 3 == 0 contribute (output subsamples h at stride 3)
//   -> skip the x gather + atomic for 2/3 of edges.
// ---------------------------------------------------------------------------
__device__ __forceinline__ void do_edge(int d, int s, const float* __restrict__ x) {
    if (d % 3 == 0) {
        atomicAdd(&g_agg[d / 3], __ldg(&x[s]));
    }
}

__global__ void scatter_kernel(const int* __restrict__ src,
                               const int* __restrict__ dst,
                               const float* __restrict__ x,
                               int nedges) {
    const int4* src4 = reinterpret_cast<const int4*>(src);
    const int4* dst4 = reinterpret_cast<const int4*>(dst);
    int t = blockIdx.x * blockDim.x + threadIdx.x;   // octet index (8 edges)
    int noct = nedges >> 3;

    if (t < noct) {
        // 2 x int4 per row = 8 edges, streaming loads
        int4 da = __ldcs(&dst4[2 * t]);
        int4 db = __ldcs(&dst4[2 * t + 1]);
        int4 sa = __ldcs(&src4[2 * t]);
        int4 sb = __ldcs(&src4[2 * t + 1]);

        do_edge(da.x, sa.x, x);
        do_edge(da.y, sa.y, x);
        do_edge(da.z, sa.z, x);
        do_edge(da.w, sa.w, x);
        do_edge(db.x, sb.x, x);
        do_edge(db.y, sb.y, x);
        do_edge(db.z, sb.z, x);
        do_edge(db.w, sb.w, x);
    }

    // Tail (nedges not a multiple of 8)
    int tail_start = noct << 3;
    int e = tail_start + t;
    if (t < 8 && e < nedges) {
        int d = __ldg(&dst[e]);
        if (d % 3 == 0) {
            int s = __ldg(&src[e]);
            atomicAdd(&g_agg[d / 3], __ldg(&x[s]));
        }
    }
}

// ---------------------------------------------------------------------------
// Kernel 3: finalize. h = agg*Wl + x[3i]*Wr, then MLP(1->2->relu->1).
// ---------------------------------------------------------------------------
__global__ void finalize_kernel(const float* __restrict__ x,
                                const float* __restrict__ Wl,
                                const float* __restrict__ Wr,
                                const float* __restrict__ W1,
                                const float* __restrict__ b1,
                                const float* __restrict__ W2,
                                const float* __restrict__ b2,
                                float* __restrict__ out,
                                int m) {
    int i = blockIdx.x * blockDim.x + threadIdx.x;
    if (i >= m) return;

    float wl = __ldg(&Wl[0]);
    float wr = __ldg(&Wr[0]);
    float w10 = __ldg(&W1[0]), w11 = __ldg(&W1[1]);
    float bb0 = __ldg(&b1[0]), bb1 = __ldg(&b1[1]);
    float w20 = __ldg(&W2[0]), w21 = __ldg(&W2[1]);
    float bb2 = __ldg(&b2[0]);

    float h = g_agg[i] * wl + __ldg(&x[3 * i]) * wr;
    float a0 = fmaxf(fmaf(h, w10, bb0), 0.0f);
    float a1 = fmaxf(fmaf(h, w11, bb1), 0.0f);
    out[i] = fmaf(a0, w20, fmaf(a1, w21, bb2));
}

// ---------------------------------------------------------------------------
// Launch
// Inputs (metadata order): x[N,1] f32, edge_index[2,E] int32 (downcast from
// int64), W_l[1,1], W_r[1,1], W1[2,1], b1[2], W2[1,2], b2[1]
// Output: float[N/3]
// ---------------------------------------------------------------------------
extern "C" void kernel_launch(void* const* d_in, const int* in_sizes, int n_in,
                              void* d_out, int out_size) {
    const float* x  = (const float*)d_in[0];
    const int* edge_index = (const int*)d_in[1];
    const float* Wl = (const float*)d_in[2];
    const float* Wr = (const float*)d_in[3];
    const float* W1 = (const float*)d_in[4];
    const float* b1 = (const float*)d_in[5];
    const float* W2 = (const float*)d_in[6];
    const float* b2 = (const float*)d_in[7];
    float* out = (float*)d_out;

    int nedges = in_sizes[1] / 2;   // E (edge_index has 2*E elements)
    int m = out_size;               // N/3 output nodes

    const int* src = edge_index;
    const int* dst = edge_index + nedges;

    // 1) zero scratch (m = 1,000,000 -> divisible by 4)
    int m4 = m / 4;
    zero_agg_kernel<<<(m4 + 255) / 256, 256>>>(m4);

    // 2) scatter: one thread per 8 edges
    int noct = nedges >> 3;
    int blocks = (noct + 255) / 256;
    scatter_kernel<<<blocks, 256>>>(src, dst, x, nedges);

    // 3) finalize
    finalize_kernel<<<(m + 255) / 256, 256>>>(x, Wl, Wr, W1, b1, W2, b2, out, m);
}

// round 4
// speedup vs baseline: 1.0792x; 1.0792x over previous
#include <cuda_runtime.h>
#include <stdint.h>

// Output nodes = N_NODES / 3 = 1,000,000
#define MAX_OUT_NODES 1000000
__device__ float g_agg[MAX_OUT_NODES];   // static zero-init; finalize re-zeros it
                                         // each call, so scatter always starts
                                         // from zeros (graph-replay invariant).

// ---------------------------------------------------------------------------
// Kernel 1: edge scatter, 8 edges per thread.
// Only edges with dst % 3 == 0 contribute (the output subsamples h at stride
// 3 before the MLP) -> skip the x gather + atomic for 2/3 of edges.
// Phased inner loop: filter all 8, issue all gathers, then all atomics, so
// the divergent L2-hit gathers overlap maximally.
// ---------------------------------------------------------------------------
__global__ void scatter_kernel(const int* __restrict__ src,
                               const int* __restrict__ dst,
                               const float* __restrict__ x,
                               int nedges) {
    const int4* src4 = reinterpret_cast<const int4*>(src);
    const int4* dst4 = reinterpret_cast<const int4*>(dst);
    int t = blockIdx.x * blockDim.x + threadIdx.x;   // octet index (8 edges)
    int noct = nedges >> 3;

    if (t < noct) {
        int4 da = __ldg(&dst4[2 * t]);
        int4 db = __ldg(&dst4[2 * t + 1]);
        int4 sa = __ldg(&src4[2 * t]);
        int4 sb = __ldg(&src4[2 * t + 1]);

        int d[8] = {da.x, da.y, da.z, da.w, db.x, db.y, db.z, db.w};
        int s[8] = {sa.x, sa.y, sa.z, sa.w, sb.x, sb.y, sb.z, sb.w};

        bool  ok[8];
        float v[8];
#pragma unroll
        for (int k = 0; k < 8; k++) {
            ok[k] = (d[k] % 3 == 0);
        }
#pragma unroll
        for (int k = 0; k < 8; k++) {
            v[k] = ok[k] ? __ldg(&x[s[k]]) : 0.0f;
        }
#pragma unroll
        for (int k = 0; k < 8; k++) {
            if (ok[k]) atomicAdd(&g_agg[d[k] / 3], v[k]);
        }
    }

    // Tail (nedges not a multiple of 8)
    int tail_start = noct << 3;
    int e = tail_start + t;
    if (t < 8 && e < nedges) {
        int dd = __ldg(&dst[e]);
        if (dd % 3 == 0) {
            int ss = __ldg(&src[e]);
            atomicAdd(&g_agg[dd / 3], __ldg(&x[ss]));
        }
    }
}

// ---------------------------------------------------------------------------
// Kernel 2: finalize. h = agg*Wl + x[3i]*Wr, then MLP(1->2->relu->1).
// Also resets g_agg[i] to 0 for the next call (replaces the zero kernel).
// ---------------------------------------------------------------------------
__global__ void finalize_kernel(const float* __restrict__ x,
                                const float* __restrict__ Wl,
                                const float* __restrict__ Wr,
                                const float* __restrict__ W1,
                                const float* __restrict__ b1,
                                const float* __restrict__ W2,
                                const float* __restrict__ b2,
                                float* __restrict__ out,
                                int m) {
    int i = blockIdx.x * blockDim.x + threadIdx.x;
    if (i >= m) return;

    float wl = __ldg(&Wl[0]);
    float wr = __ldg(&Wr[0]);
    float w10 = __ldg(&W1[0]), w11 = __ldg(&W1[1]);
    float bb0 = __ldg(&b1[0]), bb1 = __ldg(&b1[1]);
    float w20 = __ldg(&W2[0]), w21 = __ldg(&W2[1]);
    float bb2 = __ldg(&b2[0]);

    float agg = g_agg[i];
    g_agg[i] = 0.0f;                       // reset for the next launch/replay

    float h = agg * wl + __ldg(&x[3 * i]) * wr;
    float a0 = fmaxf(fmaf(h, w10, bb0), 0.0f);
    float a1 = fmaxf(fmaf(h, w11, bb1), 0.0f);
    out[i] = fmaf(a0, w20, fmaf(a1, w21, bb2));
}

// ---------------------------------------------------------------------------
// Launch
// Inputs (metadata order): x[N,1] f32, edge_index[2,E] int32 (downcast from
// int64), W_l[1,1], W_r[1,1], W1[2,1], b1[2], W2[1,2], b2[1]
// Output: float[N/3]
// ---------------------------------------------------------------------------
extern "C" void kernel_launch(void* const* d_in, const int* in_sizes, int n_in,
                              void* d_out, int out_size) {
    const float* x  = (const float*)d_in[0];
    const int* edge_index = (const int*)d_in[1];
    const float* Wl = (const float*)d_in[2];
    const float* Wr = (const float*)d_in[3];
    const float* W1 = (const float*)d_in[4];
    const float* b1 = (const float*)d_in[5];
    const float* W2 = (const float*)d_in[6];
    const float* b2 = (const float*)d_in[7];
    float* out = (float*)d_out;

    int nedges = in_sizes[1] / 2;   // E (edge_index has 2*E elements)
    int m = out_size;               // N/3 output nodes

    const int* src = edge_index;
    const int* dst = edge_index + nedges;

    // 1) scatter: one thread per 8 edges
    int noct = nedges >> 3;
    int blocks = (noct + 255) / 256;
    scatter_kernel<<<blocks, 256>>>(src, dst, x, nedges);

    // 2) finalize (also re-zeros g_agg for the next call)
    finalize_kernel<<<(m + 255) / 256, 256>>>(x, Wl, Wr, W1, b1, W2, b2, out, m);
}

// round 5
// speedup vs baseline: 1.0985x; 1.0179x over previous
#include <cuda_runtime.h>
#include <stdint.h>

// Output nodes = N_NODES / 3 = 1,000,000
#define MAX_OUT_NODES 1000000
__device__ float g_agg[MAX_OUT_NODES];   // static zero-init; finalize re-zeros it
                                         // each call, so scatter always starts
                                         // from zeros (graph-replay invariant).

// ---------------------------------------------------------------------------
// Kernel 1: edge scatter, 8 edges per thread.
// Only edges with dst % 3 == 0 contribute (the output subsamples h at stride
// 3 before the MLP) -> skip the x gather + atomic for 2/3 of edges.
// This kernel is at the L1tex lane-op floor (~1 cyc per gather/RED lane);
// the index loads and filtering are noise next to that.
// ---------------------------------------------------------------------------
__global__ void scatter_kernel(const int* __restrict__ src,
                               const int* __restrict__ dst,
                               const float* __restrict__ x,
                               int nedges) {
    const int4* src4 = reinterpret_cast<const int4*>(src);
    const int4* dst4 = reinterpret_cast<const int4*>(dst);
    int t = blockIdx.x * blockDim.x + threadIdx.x;   // octet index (8 edges)
    int noct = nedges >> 3;

    if (t < noct) {
        int4 da = __ldg(&dst4[2 * t]);
        int4 db = __ldg(&dst4[2 * t + 1]);
        int4 sa = __ldg(&src4[2 * t]);
        int4 sb = __ldg(&src4[2 * t + 1]);

        int d[8] = {da.x, da.y, da.z, da.w, db.x, db.y, db.z, db.w};
        int s[8] = {sa.x, sa.y, sa.z, sa.w, sb.x, sb.y, sb.z, sb.w};

        bool  ok[8];
        float v[8];
#pragma unroll
        for (int k = 0; k < 8; k++) {
            ok[k] = (d[k] % 3 == 0);
        }
#pragma unroll
        for (int k = 0; k < 8; k++) {
            v[k] = ok[k] ? __ldg(&x[s[k]]) : 0.0f;
        }
#pragma unroll
        for (int k = 0; k < 8; k++) {
            if (ok[k]) atomicAdd(&g_agg[d[k] / 3], v[k]);
        }
    }

    // Tail (nedges not a multiple of 8)
    int tail_start = noct << 3;
    int e = tail_start + t;
    if (t < 8 && e < nedges) {
        int dd = __ldg(&dst[e]);
        if (dd % 3 == 0) {
            int ss = __ldg(&src[e]);
            atomicAdd(&g_agg[dd / 3], __ldg(&x[ss]));
        }
    }
}

// ---------------------------------------------------------------------------
// Kernel 2: finalize, 4 outputs per thread, fully vectorized.
// h = agg*Wl + x[3i]*Wr, then MLP(1->2->relu->1). Also resets g_agg.
// Per thread: 1x float4 agg load, 3x float4 x load (coalesced, covers
// x[12i .. 12i+11]), 1x float4 out store, 1x float4 agg-zero store.
// ---------------------------------------------------------------------------
__global__ void finalize_kernel(const float* __restrict__ x,
                                const float* __restrict__ Wl,
                                const float* __restrict__ Wr,
                                const float* __restrict__ W1,
                                const float* __restrict__ b1,
                                const float* __restrict__ W2,
                                const float* __restrict__ b2,
                                float* __restrict__ out,
                                int m4) {       // m/4 quads
    int q = blockIdx.x * blockDim.x + threadIdx.x;
    if (q >= m4) return;

    float wl = __ldg(&Wl[0]);
    float wr = __ldg(&Wr[0]);
    float w10 = __ldg(&W1[0]), w11 = __ldg(&W1[1]);
    float bb0 = __ldg(&b1[0]), bb1 = __ldg(&b1[1]);
    float w20 = __ldg(&W2[0]), w21 = __ldg(&W2[1]);
    float bb2 = __ldg(&b2[0]);

    float4* agg4 = reinterpret_cast<float4*>(g_agg);
    const float4* x4 = reinterpret_cast<const float4*>(x);

    float4 a = agg4[q];
    agg4[q] = make_float4(0.f, 0.f, 0.f, 0.f);    // reset for next call/replay

    // outputs i = 4q..4q+3 need x[12q], x[12q+3], x[12q+6], x[12q+9]
    float4 xa = __ldg(&x4[3 * q]);       // x[12q .. 12q+3]
    float4 xb = __ldg(&x4[3 * q + 1]);   // x[12q+4 .. 12q+7]
    float4 xc = __ldg(&x4[3 * q + 2]);   // x[12q+8 .. 12q+11]

    float xr0 = xa.x;   // x[12q+0]
    float xr1 = xa.w;   // x[12q+3]
    float xr2 = xb.z;   // x[12q+6]
    float xr3 = xc.y;   // x[12q+9]

    float h0 = fmaf(a.x, wl, xr0 * wr);
    float h1 = fmaf(a.y, wl, xr1 * wr);
    float h2 = fmaf(a.z, wl, xr2 * wr);
    float h3 = fmaf(a.w, wl, xr3 * wr);

    float4 o;
    {
        float p0 = fmaxf(fmaf(h0, w10, bb0), 0.0f);
        float p1 = fmaxf(fmaf(h0, w11, bb1), 0.0f);
        o.x = fmaf(p0, w20, fmaf(p1, w21, bb2));
    }
    {
        float p0 = fmaxf(fmaf(h1, w10, bb0), 0.0f);
        float p1 = fmaxf(fmaf(h1, w11, bb1), 0.0f);
        o.y = fmaf(p0, w20, fmaf(p1, w21, bb2));
    }
    {
        float p0 = fmaxf(fmaf(h2, w10, bb0), 0.0f);
        float p1 = fmaxf(fmaf(h2, w11, bb1), 0.0f);
        o.z = fmaf(p0, w20, fmaf(p1, w21, bb2));
    }
    {
        float p0 = fmaxf(fmaf(h3, w10, bb0), 0.0f);
        float p1 = fmaxf(fmaf(h3, w11, bb1), 0.0f);
        o.w = fmaf(p0, w20, fmaf(p1, w21, bb2));
    }

    reinterpret_cast<float4*>(out)[q] = o;
}

// ---------------------------------------------------------------------------
// Launch
// Inputs (metadata order): x[N,1] f32, edge_index[2,E] int32 (downcast from
// int64), W_l[1,1], W_r[1,1], W1[2,1], b1[2], W2[1,2], b2[1]
// Output: float[N/3]; out_size = 1,000,000 (divisible by 4).
// ---------------------------------------------------------------------------
extern "C" void kernel_launch(void* const* d_in, const int* in_sizes, int n_in,
                              void* d_out, int out_size) {
    const float* x  = (const float*)d_in[0];
    const int* edge_index = (const int*)d_in[1];
    const float* Wl = (const float*)d_in[2];
    const float* Wr = (const float*)d_in[3];
    const float* W1 = (const float*)d_in[4];
    const float* b1 = (const float*)d_in[5];
    const float* W2 = (const float*)d_in[6];
    const float* b2 = (const float*)d_in[7];
    float* out = (float*)d_out;

    int nedges = in_sizes[1] / 2;   // E (edge_index has 2*E elements)
    int m = out_size;               // N/3 output nodes
    int m4 = m / 4;

    const int* src = edge_index;
    const int* dst = edge_index + nedges;

    // 1) scatter: one thread per 8 edges
    int noct = nedges >> 3;
    int blocks = (noct + 255) / 256;
    scatter_kernel<<<blocks, 256>>>(src, dst, x, nedges);

    // 2) finalize (vectorized; also re-zeros g_agg for the next call)
    finalize_kernel<<<(m4 + 255) / 256, 256>>>(x, Wl, Wr, W1, b1, W2, b2, out, m4);
}

// round 6
// speedup vs baseline: 1.0987x; 1.0002x over previous
#include <cuda_runtime.h>
#include <stdint.h>

// Output nodes = N_NODES / 3 = 1,000,000
#define MAX_OUT_NODES 1000000
__device__ float g_agg[MAX_OUT_NODES];   // static zero-init; finalize re-zeros it
                                         // each call, so scatter always starts
                                         // from zeros (graph-replay invariant).

// ---------------------------------------------------------------------------
// Kernel 1: edge scatter, 8 edges per thread.
// Only edges with dst % 3 == 0 contribute (the output subsamples h at stride
// 3 before the MLP) -> skip the x gather + atomic for 2/3 of edges.
// This kernel sits at the L1tex lane-op floor (~1-1.3 cyc per divergent
// gather / spread-RED lane): 32M lane-ops / 148 SMs ~ 123 us. Untouchable
// without changing the algorithm.
// ---------------------------------------------------------------------------
__global__ void scatter_kernel(const int* __restrict__ src,
                               const int* __restrict__ dst,
                               const float* __restrict__ x,
                               int nedges) {
    const int4* src4 = reinterpret_cast<const int4*>(src);
    const int4* dst4 = reinterpret_cast<const int4*>(dst);
    int t = blockIdx.x * blockDim.x + threadIdx.x;   // octet index (8 edges)
    int noct = nedges >> 3;

    if (t < noct) {
        int4 da = __ldg(&dst4[2 * t]);
        int4 db = __ldg(&dst4[2 * t + 1]);
        int4 sa = __ldg(&src4[2 * t]);
        int4 sb = __ldg(&src4[2 * t + 1]);

        int d[8] = {da.x, da.y, da.z, da.w, db.x, db.y, db.z, db.w};
        int s[8] = {sa.x, sa.y, sa.z, sa.w, sb.x, sb.y, sb.z, sb.w};

        bool  ok[8];
        float v[8];
#pragma unroll
        for (int k = 0; k < 8; k++) {
            ok[k] = (d[k] % 3 == 0);
        }
#pragma unroll
        for (int k = 0; k < 8; k++) {
            v[k] = ok[k] ? __ldg(&x[s[k]]) : 0.0f;
        }
#pragma unroll
        for (int k = 0; k < 8; k++) {
            if (ok[k]) atomicAdd(&g_agg[d[k] / 3], v[k]);
        }
    }

    // Tail (nedges not a multiple of 8)
    int tail_start = noct << 3;
    int e = tail_start + t;
    if (t < 8 && e < nedges) {
        int dd = __ldg(&dst[e]);
        if (dd % 3 == 0) {
            int ss = __ldg(&src[e]);
            atomicAdd(&g_agg[dd / 3], __ldg(&x[ss]));
        }
    }
}

// ---------------------------------------------------------------------------
// Kernel 2: finalize, 8 outputs per thread (2 float4 quads), all loads
// issued before any consumption for MLP ~ 8-10 (latency-bound fix).
// h = agg*Wl + x[3i]*Wr, then MLP(1->2->relu->1). Also resets g_agg.
// ---------------------------------------------------------------------------
__device__ __forceinline__ float4 mlp4(float4 a, float x0, float x1, float x2,
                                       float x3, float wl, float wr,
                                       float w10, float w11, float bb0,
                                       float bb1, float w20, float w21,
                                       float bb2) {
    float h0 = fmaf(a.x, wl, x0 * wr);
    float h1 = fmaf(a.y, wl, x1 * wr);
    float h2 = fmaf(a.z, wl, x2 * wr);
    float h3 = fmaf(a.w, wl, x3 * wr);
    float4 o;
    o.x = fmaf(fmaxf(fmaf(h0, w10, bb0), 0.f), w20,
               fmaf(fmaxf(fmaf(h0, w11, bb1), 0.f), w21, bb2));
    o.y = fmaf(fmaxf(fmaf(h1, w10, bb0), 0.f), w20,
               fmaf(fmaxf(fmaf(h1, w11, bb1), 0.f), w21, bb2));
    o.z = fmaf(fmaxf(fmaf(h2, w10, bb0), 0.f), w20,
               fmaf(fmaxf(fmaf(h2, w11, bb1), 0.f), w21, bb2));
    o.w = fmaf(fmaxf(fmaf(h3, w10, bb0), 0.f), w20,
               fmaf(fmaxf(fmaf(h3, w11, bb1), 0.f), w21, bb2));
    return o;
}

__global__ void finalize_kernel(const float* __restrict__ x,
                                const float* __restrict__ Wl,
                                const float* __restrict__ Wr,
                                const float* __restrict__ W1,
                                const float* __restrict__ b1,
                                const float* __restrict__ W2,
                                const float* __restrict__ b2,
                                float* __restrict__ out,
                                int m8) {       // m/8 octets
    int t = blockIdx.x * blockDim.x + threadIdx.x;
    if (t >= m8) return;

    float4* agg4 = reinterpret_cast<float4*>(g_agg);
    const float4* x4 = reinterpret_cast<const float4*>(x);
    float4* out4 = reinterpret_cast<float4*>(out);

    int q0 = 2 * t;          // first quad
    int q1 = 2 * t + 1;      // second quad

    // ---- issue ALL loads up front (8 independent LDG.128) ----
    float4 a0 = agg4[q0];
    float4 a1 = agg4[q1];
    float4 xa0 = __ldg(&x4[3 * q0]);
    float4 xb0 = __ldg(&x4[3 * q0 + 1]);
    float4 xc0 = __ldg(&x4[3 * q0 + 2]);
    float4 xa1 = __ldg(&x4[3 * q1]);
    float4 xb1 = __ldg(&x4[3 * q1 + 1]);
    float4 xc1 = __ldg(&x4[3 * q1 + 2]);

    // reset agg for next call/replay
    float4 z = make_float4(0.f, 0.f, 0.f, 0.f);
    agg4[q0] = z;
    agg4[q1] = z;

    float wl = __ldg(&Wl[0]);
    float wr = __ldg(&Wr[0]);
    float w10 = __ldg(&W1[0]), w11 = __ldg(&W1[1]);
    float bb0 = __ldg(&b1[0]), bb1 = __ldg(&b1[1]);
    float w20 = __ldg(&W2[0]), w21 = __ldg(&W2[1]);
    float bb2 = __ldg(&b2[0]);

    // quad 0 roots: x[12q0], x[12q0+3], x[12q0+6], x[12q0+9]
    out4[q0] = mlp4(a0, xa0.x, xa0.w, xb0.z, xc0.y,
                    wl, wr, w10, w11, bb0, bb1, w20, w21, bb2);
    // quad 1 roots
    out4[q1] = mlp4(a1, xa1.x, xa1.w, xb1.z, xc1.y,
                    wl, wr, w10, w11, bb0, bb1, w20, w21, bb2);
}

// ---------------------------------------------------------------------------
// Launch
// Inputs (metadata order): x[N,1] f32, edge_index[2,E] int32 (downcast from
// int64), W_l[1,1], W_r[1,1], W1[2,1], b1[2], W2[1,2], b2[1]
// Output: float[N/3]; out_size = 1,000,000 (divisible by 8).
// ---------------------------------------------------------------------------
extern "C" void kernel_launch(void* const* d_in, const int* in_sizes, int n_in,
                              void* d_out, int out_size) {
    const float* x  = (const float*)d_in[0];
    const int* edge_index = (const int*)d_in[1];
    const float* Wl = (const float*)d_in[2];
    const float* Wr = (const float*)d_in[3];
    const float* W1 = (const float*)d_in[4];
    const float* b1 = (const float*)d_in[5];
    const float* W2 = (const float*)d_in[6];
    const float* b2 = (const float*)d_in[7];
    float* out = (float*)d_out;

    int nedges = in_sizes[1] / 2;   // E (edge_index has 2*E elements)
    int m = out_size;               // N/3 output nodes
    int m8 = m / 8;

    const int* src = edge_index;
    const int* dst = edge_index + nedges;

    // 1) scatter: one thread per 8 edges
    int noct = nedges >> 3;
    int blocks = (noct + 255) / 256;
    scatter_kernel<<<blocks, 256>>>(src, dst, x, nedges);

    // 2) finalize: one thread per 8 outputs (also re-zeros g_agg)
    finalize_kernel<<<(m8 + 255) / 256, 256>>>(x, Wl, Wr, W1, b1, W2, b2, out, m8);
}